// round 9
// baseline (speedup 1.0000x reference)
#include <cuda_runtime.h>
#include <cstdint>
#include <cstddef>

// ---------------- problem constants ----------------
#define BSZ   2
#define LSEQ  2048
#define DIMV  472          // DIM == V
#define ED    944
#define NST   16
#define RK    30
#define NDEPTH 8
#define MROWS (BSZ*LSEQ)   // 4096
#define XZW   (2*ED)       // 1888
#define DBLW  (RK + 2*NST) // 62

// scan chunking: 16 chunks of 128 steps, one warp per chunk
#define SCH   16
#define SCL   (LSEQ/SCH)   // 128

// prep kernel K-chunk: 944 = 8 * 118
#define PKC   118

// ---------------- scratch (device globals: allocation-free) ----------------
__device__ float g_h[(size_t)MROWS*DIMV];
__device__ float g_xz[(size_t)MROWS*XZW];
__device__ float g_xc[2][(size_t)MROWS*ED];
__device__ float g_dbl[2][(size_t)MROWS*DBLW];
__device__ float g_delta[2][(size_t)MROWS*ED];
__device__ float g_y[2][(size_t)MROWS*ED];

// ---------------- patch embed ----------------
__global__ void patch_kernel(const float* __restrict__ x,
                             const float* __restrict__ pw,
                             const float* __restrict__ pb)
{
    int i = blockIdx.x*blockDim.x + threadIdx.x;
    if (i >= MROWS*DIMV) return;
    int m = i / DIMV, v = i - m*DIMV;
    const float* xr = x + (size_t)m*9;
    const float* wr = pw + (size_t)v*9;
    float s = pb[v];
#pragma unroll
    for (int k = 0; k < 9; k++) s = fmaf(xr[k], wr[k], s);
    g_h[i] = s;
}

__device__ __forceinline__ float4 ld4_guard(const float* p, int k0, int K)
{
    float4 v = make_float4(0.f, 0.f, 0.f, 0.f);
    if (k0 + 3 < K) v = *(const float4*)p;
    else if (k0 < K) {
        v.x = p[0];
        if (k0 + 1 < K) v.y = p[1];
        if (k0 + 2 < K) v.z = p[2];
    }
    return v;
}

// ---------------- tf32-split helpers ----------------
__device__ __forceinline__ uint32_t to_tf32(float a) {
    uint32_t u;
    asm("cvt.rna.tf32.f32 %0, %1;" : "=r"(u) : "f"(a));
    return u;
}
__device__ __forceinline__ void split_tf32(float a, uint32_t& h, uint32_t& l) {
    h = to_tf32(a);
    l = to_tf32(a - __uint_as_float(h));
}

#define MMA_TF32(d, a, b) \
    asm volatile("mma.sync.aligned.m16n8k8.row.col.f32.tf32.tf32.f32 " \
        "{%0,%1,%2,%3}, {%4,%5,%6,%7}, {%8,%9}, {%0,%1,%2,%3};" \
        : "+f"((d)[0]), "+f"((d)[1]), "+f"((d)[2]), "+f"((d)[3]) \
        : "r"((a)[0]), "r"((a)[1]), "r"((a)[2]), "r"((a)[3]), \
          "r"((b)[0]), "r"((b)[1]))

// ---------------- tensor GEMM via mma.sync (tf32 3-pass split) -------------
// C[M,N] = (A(+A2))[M,K] * W[N,K]^T (+C).  M multiple of 128; N,K guarded.
// CTA tile 128x128, K chunk 16.  8 warps: warp tile 32 (m) x 64 (n).
#define TGKC 16
#define SAS  20   // smem row stride in floats (16 + 4 pad): conflict-free frag loads

__global__ __launch_bounds__(256, 1)
void tgemm(const float* __restrict__ A, const float* __restrict__ A2,
           const float* __restrict__ W, float* __restrict__ C,
           int N, int K, int accum)
{
    __shared__ float Ah[128*SAS];
    __shared__ float Al[128*SAS];
    __shared__ float Bh[128*SAS];
    __shared__ float Bl[128*SAS];

    const int tid = threadIdx.x;
    const int bm  = blockIdx.y * 128;
    const int bn  = blockIdx.x * 128;
    const int lr  = tid >> 1;              // 0..127 (row of A/B tile)
    const int lc  = (tid & 1) * 8;         // 0 or 8 (k offset)
    const int nck = (K + TGKC - 1) / TGKC;

    const int lane = tid & 31, wid = tid >> 5;
    const int g = lane >> 2, t = lane & 3;
    const int wm = (wid >> 1) * 32;        // warp row base within tile
    const int wn = (wid & 1)  * 64;        // warp col base within tile

    const float* arow  = A + (size_t)(bm + lr) * K;
    const float* a2row = A2 ? A2 + (size_t)(bm + lr) * K : (const float*)0;
    const bool   wv    = (bn + lr) < N;
    const float* wrow  = W + (size_t)(bn + lr) * K;

    float acc[2][8][4];
#pragma unroll
    for (int mt = 0; mt < 2; mt++)
#pragma unroll
        for (int nt = 0; nt < 8; nt++)
#pragma unroll
            for (int q = 0; q < 4; q++) acc[mt][nt][q] = 0.f;

    float4 va[2], vw[2];

    // prologue: load chunk 0 into regs
    {
        int k0 = lc;
#pragma unroll
        for (int i = 0; i < 2; i++) {
            int gk = k0 + i*4;
            va[i] = ld4_guard(arow + gk, gk, K);
            if (a2row) {
                float4 v2 = ld4_guard(a2row + gk, gk, K);
                va[i].x += v2.x; va[i].y += v2.y; va[i].z += v2.z; va[i].w += v2.w;
            }
            vw[i] = wv ? ld4_guard(wrow + gk, gk, K) : make_float4(0.f,0.f,0.f,0.f);
        }
    }

    for (int ck = 0; ck < nck; ck++) {
        // split current regs to smem planes
#pragma unroll
        for (int i = 0; i < 2; i++) {
            int idx = lr*SAS + lc + i*4;
            uint32_t h0,l0,h1,l1,h2,l2,h3,l3;
            split_tf32(va[i].x, h0, l0); split_tf32(va[i].y, h1, l1);
            split_tf32(va[i].z, h2, l2); split_tf32(va[i].w, h3, l3);
            *(uint4*)&Ah[idx] = make_uint4(h0,h1,h2,h3);
            *(uint4*)&Al[idx] = make_uint4(l0,l1,l2,l3);
            split_tf32(vw[i].x, h0, l0); split_tf32(vw[i].y, h1, l1);
            split_tf32(vw[i].z, h2, l2); split_tf32(vw[i].w, h3, l3);
            *(uint4*)&Bh[idx] = make_uint4(h0,h1,h2,h3);
            *(uint4*)&Bl[idx] = make_uint4(l0,l1,l2,l3);
        }
        __syncthreads();

        // prefetch next chunk into regs (overlaps with MMA below)
        if (ck + 1 < nck) {
            int k0 = (ck+1)*TGKC + lc;
#pragma unroll
            for (int i = 0; i < 2; i++) {
                int gk = k0 + i*4;
                va[i] = ld4_guard(arow + gk, gk, K);
                if (a2row) {
                    float4 v2 = ld4_guard(a2row + gk, gk, K);
                    va[i].x += v2.x; va[i].y += v2.y; va[i].z += v2.z; va[i].w += v2.w;
                }
                vw[i] = wv ? ld4_guard(wrow + gk, gk, K) : make_float4(0.f,0.f,0.f,0.f);
            }
        }

        // compute: 2 k8 steps
#pragma unroll
        for (int kk = 0; kk < TGKC; kk += 8) {
            uint32_t ah[2][4], al[2][4];
#pragma unroll
            for (int mt = 0; mt < 2; mt++) {
                int base = (wm + mt*16 + g)*SAS + kk + t;
                ah[mt][0] = __float_as_uint(Ah[base]);
                ah[mt][1] = __float_as_uint(Ah[base + 8*SAS]);
                ah[mt][2] = __float_as_uint(Ah[base + 4]);
                ah[mt][3] = __float_as_uint(Ah[base + 8*SAS + 4]);
                al[mt][0] = __float_as_uint(Al[base]);
                al[mt][1] = __float_as_uint(Al[base + 8*SAS]);
                al[mt][2] = __float_as_uint(Al[base + 4]);
                al[mt][3] = __float_as_uint(Al[base + 8*SAS + 4]);
            }
            uint32_t bh[8][2], bl[8][2];
#pragma unroll
            for (int nt = 0; nt < 8; nt++) {
                int nb = (wn + nt*8 + g)*SAS + kk + t;
                bh[nt][0] = __float_as_uint(Bh[nb]);
                bh[nt][1] = __float_as_uint(Bh[nb + 4]);
                bl[nt][0] = __float_as_uint(Bl[nb]);
                bl[nt][1] = __float_as_uint(Bl[nb + 4]);
            }
#pragma unroll
            for (int mt = 0; mt < 2; mt++)
#pragma unroll
                for (int nt = 0; nt < 8; nt++)
                    MMA_TF32(acc[mt][nt], ah[mt], bh[nt]);
#pragma unroll
            for (int mt = 0; mt < 2; mt++)
#pragma unroll
                for (int nt = 0; nt < 8; nt++)
                    MMA_TF32(acc[mt][nt], ah[mt], bl[nt]);
#pragma unroll
            for (int mt = 0; mt < 2; mt++)
#pragma unroll
                for (int nt = 0; nt < 8; nt++)
                    MMA_TF32(acc[mt][nt], al[mt], bh[nt]);
        }
        __syncthreads();
    }

    // epilogue
#pragma unroll
    for (int mt = 0; mt < 2; mt++) {
        int row0 = bm + wm + mt*16 + g;
#pragma unroll
        for (int half = 0; half < 2; half++) {
            int rowg = row0 + half*8;
            float* crow = C + (size_t)rowg * N;
#pragma unroll
            for (int nt = 0; nt < 8; nt++) {
                int col = bn + wn + nt*8 + t*2;
                float v0 = acc[mt][nt][half*2 + 0];
                float v1 = acc[mt][nt][half*2 + 1];
                if (col + 1 < N) {
                    float2 v = make_float2(v0, v1);
                    if (accum) {
                        float2 o = *(const float2*)&crow[col];
                        v.x += o.x; v.y += o.y;
                    }
                    *(float2*)&crow[col] = v;
                } else if (col < N) {
                    float v = v0;
                    if (accum) v += crow[col];
                    crow[col] = v;
                }
            }
        }
    }
}

// ---------------- fused prep: depthwise conv + SiLU + xproj + dt -----------
// One block = 16 sequence rows of one direction.  K chunked 8x118.
// Produces: g_xc[dir], g_dbl[dir] (cols B,C for scan), g_delta[dir].
__global__ __launch_bounds__(256)
void prep_kernel(const float* __restrict__ cw, const float* __restrict__ cb,
                 const float* __restrict__ xpw,
                 const float* __restrict__ dtw, const float* __restrict__ dtb)
{
    __shared__ float xcs[16][PKC+3];    // stride 121 (gcd(121%32,32)=1)
    __shared__ float wss[62][PKC+3];
    __shared__ float dbls[16][64];

    const int dir = blockIdx.y;
    const int m0  = blockIdx.x * 16;
    const int tid = threadIdx.x;
    const int nn  = tid & 63;
    const int rq  = tid >> 6;           // 0..3 -> rows rq*4..rq*4+3

    float*       xc_out = &g_xc[dir][0];
    float*       dbl_o  = &g_dbl[dir][0];
    float*       del_o  = &g_delta[dir][0];
    const float* xz     = g_xz;

    float acc[4] = {0.f, 0.f, 0.f, 0.f};

    for (int k0 = 0; k0 < ED; k0 += PKC) {
        // stage 1: conv + SiLU for columns [k0, k0+118)
        for (int it = tid; it < 16*PKC; it += 256) {
            int r  = it / PKC, kk = it - r*PKC;
            int e  = k0 + kk;
            int m  = m0 + r;
            int t  = m & (LSEQ-1);
            float w0 = cw[e*4+0], w1 = cw[e*4+1], w2 = cw[e*4+2], w3 = cw[e*4+3];
            float s = xz[(size_t)m*XZW + e] * w3;
            if (dir == 0) {
                if (t >= 1) s = fmaf(xz[(size_t)(m-1)*XZW + e], w2, s);
                if (t >= 2) s = fmaf(xz[(size_t)(m-2)*XZW + e], w1, s);
                if (t >= 3) s = fmaf(xz[(size_t)(m-3)*XZW + e], w0, s);
            } else {
                if (t+1 < LSEQ) s = fmaf(xz[(size_t)(m+1)*XZW + e], w2, s);
                if (t+2 < LSEQ) s = fmaf(xz[(size_t)(m+2)*XZW + e], w1, s);
                if (t+3 < LSEQ) s = fmaf(xz[(size_t)(m+3)*XZW + e], w0, s);
            }
            s += cb[e];
            float sv = s / (1.f + __expf(-s));
            xcs[r][kk] = sv;
            xc_out[(size_t)m*ED + e] = sv;
        }
        // stage 2: stage W chunk
        for (int it = tid; it < 62*PKC; it += 256) {
            int n2 = it / PKC, kk = it - n2*PKC;
            wss[n2][kk] = xpw[(size_t)n2*ED + k0 + kk];
        }
        __syncthreads();
        // stage 3: accumulate dbl
        if (nn < 62) {
#pragma unroll 2
            for (int k = 0; k < PKC; k++) {
                float w = wss[nn][k];
                acc[0] = fmaf(xcs[rq*4+0][k], w, acc[0]);
                acc[1] = fmaf(xcs[rq*4+1][k], w, acc[1]);
                acc[2] = fmaf(xcs[rq*4+2][k], w, acc[2]);
                acc[3] = fmaf(xcs[rq*4+3][k], w, acc[3]);
            }
        }
        __syncthreads();
    }

    // write dbl (global for scan; smem for dt phase)
    if (nn < 62) {
#pragma unroll
        for (int i = 0; i < 4; i++) {
            int r = rq*4 + i;
            dbls[r][nn] = acc[i];
            dbl_o[(size_t)(m0+r)*DBLW + nn] = acc[i];
        }
    }
    __syncthreads();

    // dt phase: delta[16][944] = softplus(dbl[:, :30] @ dtw^T + b)
    for (int j = tid; j < ED; j += 256) {
        float wj[RK];
        const float* wr = dtw + (size_t)j*RK;
#pragma unroll
        for (int k = 0; k < RK; k += 2) {
            float2 v = *(const float2*)&wr[k];
            wj[k] = v.x; wj[k+1] = v.y;
        }
        float bj = dtb[j];
#pragma unroll 4
        for (int r = 0; r < 16; r++) {
            float a = bj;
#pragma unroll
            for (int k = 0; k < RK; k++) a = fmaf(dbls[r][k], wj[k], a);
            float sp = fmaxf(a, 0.f) + log1pf(__expf(-fabsf(a)));
            del_o[(size_t)(m0+r)*ED + j] = sp;
        }
    }
}

// ---------------- chunked parallel selective scan (pointer-walking) --------
__global__ __launch_bounds__(512)
void scan_kernel(const float* __restrict__ delta0, const float* __restrict__ xc0,
                 const float* __restrict__ dbl0,  const float* __restrict__ Alog,
                 const float* __restrict__ Dp)
{
    int dir = blockIdx.y;
    const float* delta = delta0 + (size_t)dir * MROWS * ED;
    const float* xc    = xc0    + (size_t)dir * MROWS * ED;
    const float* dbl   = dbl0   + (size_t)dir * MROWS * DBLW;
    float*       yout  = &g_y[dir][0];

    __shared__ float sH[SCH][32];
    __shared__ float sP[SCH][32];

    const int wid  = threadIdx.x >> 5;     // chunk index 0..15
    const int lane = threadIdx.x & 31;
    const int half = lane >> 4;
    const int n    = lane & 15;
    const int c    = blockIdx.x * 2 + half;   // channel 0..1887
    const int b    = c / ED;
    const int e    = c - b*ED;

    const float An2 = -__expf(Alog[e*NST + n]) * 1.4426950408889634f;
    const float Dv  = Dp[e];
    const size_t mbase = (size_t)b * LSEQ;
    const int t0     = wid * SCL;
    const int tstart = dir ? (LSEQ-1 - t0) : t0;
    const ptrdiff_t sE = dir ? -(ptrdiff_t)ED   : (ptrdiff_t)ED;
    const ptrdiff_t sD = dir ? -(ptrdiff_t)DBLW : (ptrdiff_t)DBLW;
    const ptrdiff_t sZ = dir ? -(ptrdiff_t)XZW  : (ptrdiff_t)XZW;
    const size_t mrow = mbase + tstart;

    // ---- pass A: local scan, track product of dA ----
    {
        const float* pd = delta + mrow*ED + e;
        const float* px = xc    + mrow*ED + e;
        const float* pb = dbl   + mrow*DBLW + RK + n;
        float h = 0.f, P = 1.f;
#pragma unroll 4
        for (int i = 0; i < SCL; i++) {
            float dlt = *pd, xv = *px, Bn = *pb;
            float dA  = exp2f(dlt * An2);
            h = fmaf(dA, h, dlt * xv * Bn);
            P *= dA;
            pd += sE; px += sE; pb += sD;
        }
        sH[wid][lane] = h;
        sP[wid][lane] = P;
    }
    __syncthreads();

    // ---- combine: incoming state for this chunk ----
    float hin = 0.f;
    for (int j = 0; j < wid; j++)
        hin = fmaf(sP[j][lane], hin, sH[j][lane]);

    // ---- pass B: replay chunk from hin, emit y ----
    {
        const float* pd = delta + mrow*ED + e;
        const float* px = xc    + mrow*ED + e;
        const float* pb = dbl   + mrow*DBLW + RK + n;
        const float* pz = g_xz + ED + mrow*XZW + e;
        float*       py = yout + mrow*ED + e;
        float h = hin;
#pragma unroll 2
        for (int i = 0; i < SCL; i++) {
            float dlt = *pd, xv = *px, Bn = *pb, Cn = pb[NST];
            float dA  = exp2f(dlt * An2);
            h = fmaf(dA, h, dlt * xv * Bn);
            float p = h * Cn;
            p += __shfl_xor_sync(0xffffffffu, p, 8, 16);
            p += __shfl_xor_sync(0xffffffffu, p, 4, 16);
            p += __shfl_xor_sync(0xffffffffu, p, 2, 16);
            p += __shfl_xor_sync(0xffffffffu, p, 1, 16);
            if (n == 0) {
                float zv = *pz;
                float sz = zv / (1.f + __expf(-zv));
                *py = (p + Dv*xv) * sz;
            }
            pd += sE; px += sE; pb += sD; pz += sZ; py += sE;
        }
    }
}

// ---------------- host orchestration ----------------
struct BlkP { const float *ip, *cw, *cb, *xp, *dw, *db, *al, *dd, *op; };

static void run_block_host(const BlkP& p, bool bidir,
                           float* hbuf, float* xzbuf,
                           float* xc0, float* dbl0, float* de0,
                           float* y0, float* y1)
{
    int ndir = bidir ? 2 : 1;
    // xz = h @ inproj^T (shared: inproj(flip(x)) = flip(xz))
    tgemm<<<dim3(15, 32), 256>>>(hbuf, nullptr, p.ip, xzbuf, XZW, DIMV, 0);
    // fused conv + SiLU + xproj + dt
    prep_kernel<<<dim3(MROWS/16, ndir), 256>>>(p.cw, p.cb, p.xp, p.dw, p.db);
    scan_kernel<<<dim3(944, ndir), 512>>>(de0, xc0, dbl0, p.al, p.dd);
    // h += (y0 [+ y1]) @ outproj^T
    tgemm<<<dim3(4, 32), 256>>>(y0, bidir ? y1 : nullptr, p.op, hbuf, DIMV, ED, 1);
}

extern "C" void kernel_launch(void* const* d_in, const int* in_sizes, int n_in,
                              void* d_out, int out_size)
{
    const float* x   = (const float*)d_in[0];
    const float* pw  = (const float*)d_in[1];
    const float* pb  = (const float*)d_in[2];
    const float* lmw = (const float*)d_in[3];
    const float* P[3][9];
    for (int g = 0; g < 3; g++)
        for (int i = 0; i < 9; i++)
            P[g][i] = (const float*)d_in[4 + g*9 + i];

    float *hbuf, *xzbuf, *xcb, *dblb, *deb, *ybuf;
    cudaGetSymbolAddress((void**)&hbuf,  g_h);
    cudaGetSymbolAddress((void**)&xzbuf, g_xz);
    cudaGetSymbolAddress((void**)&xcb,   g_xc);
    cudaGetSymbolAddress((void**)&dblb,  g_dbl);
    cudaGetSymbolAddress((void**)&deb,   g_delta);
    cudaGetSymbolAddress((void**)&ybuf,  g_y);
    float* y0 = ybuf;
    float* y1 = ybuf + (size_t)MROWS*ED;

    patch_kernel<<<(MROWS*DIMV + 255)/256, 256>>>(x, pw, pb);

    {
        BlkP p = { P[0][0], P[0][1], P[0][2], P[0][3], P[0][4], P[0][5], P[0][6], P[0][7], P[0][8] };
        run_block_host(p, true, hbuf, xzbuf, xcb, dblb, deb, y0, y1);
    }
    for (int l = 0; l < NDEPTH; l++) {
        BlkP p = {
            P[1][0] + (size_t)l*XZW*DIMV,
            P[1][1] + (size_t)l*ED*4,
            P[1][2] + (size_t)l*ED,
            P[1][3] + (size_t)l*DBLW*ED,
            P[1][4] + (size_t)l*ED*RK,
            P[1][5] + (size_t)l*ED,
            P[1][6] + (size_t)l*ED*NST,
            P[1][7] + (size_t)l*ED,
            P[1][8] + (size_t)l*DIMV*ED
        };
        run_block_host(p, false, hbuf, xzbuf, xcb, dblb, deb, y0, y1);
    }
    {
        BlkP p = { P[2][0], P[2][1], P[2][2], P[2][3], P[2][4], P[2][5], P[2][6], P[2][7], P[2][8] };
        run_block_host(p, true, hbuf, xzbuf, xcb, dblb, deb, y0, y1);
    }

    tgemm<<<dim3(4, 32), 256>>>(hbuf, nullptr, lmw, (float*)d_out, DIMV, DIMV, 0);
}

// round 11
// speedup vs baseline: 1.2135x; 1.2135x over previous
#include <cuda_runtime.h>
#include <cstdint>
#include <cstddef>

// ---------------- problem constants ----------------
#define BSZ   2
#define LSEQ  2048
#define DIMV  472          // DIM == V
#define ED    944
#define NST   16
#define RK    30
#define NDEPTH 8
#define MROWS (BSZ*LSEQ)   // 4096
#define XZW   (2*ED)       // 1888
#define DBLW  (RK + 2*NST) // 62

// scan chunking: 16 chunks of 128 steps, one warp per chunk
#define SCH   16
#define SCL   (LSEQ/SCH)   // 128

// ---------------- scratch (device globals: allocation-free) ----------------
__device__ float  g_h[(size_t)MROWS*DIMV];
__device__ float  g_xz[(size_t)MROWS*XZW];
__device__ float  g_xc[2][(size_t)MROWS*ED];
__device__ float  g_dbl[2][(size_t)MROWS*DBLW];
__device__ float4 g_dx[2][(size_t)MROWS*ED];     // (delta, delta*xv, D*xv, silu(z))
__device__ float2 g_bc[2][(size_t)MROWS*NST];    // (B_n, C_n)
__device__ float  g_y[2][(size_t)MROWS*ED];

// ---------------- patch embed ----------------
__global__ void patch_kernel(const float* __restrict__ x,
                             const float* __restrict__ pw,
                             const float* __restrict__ pb)
{
    int i = blockIdx.x*blockDim.x + threadIdx.x;
    if (i >= MROWS*DIMV) return;
    int m = i / DIMV, v = i - m*DIMV;
    const float* xr = x + (size_t)m*9;
    const float* wr = pw + (size_t)v*9;
    float s = pb[v];
#pragma unroll
    for (int k = 0; k < 9; k++) s = fmaf(xr[k], wr[k], s);
    g_h[i] = s;
}

__device__ __forceinline__ float4 ld4_guard(const float* p, int k0, int K)
{
    float4 v = make_float4(0.f, 0.f, 0.f, 0.f);
    if (k0 + 3 < K) v = *(const float4*)p;
    else if (k0 < K) {
        v.x = p[0];
        if (k0 + 1 < K) v.y = p[1];
        if (k0 + 2 < K) v.z = p[2];
    }
    return v;
}

// ---------------- tf32-split helpers ----------------
__device__ __forceinline__ uint32_t to_tf32(float a) {
    uint32_t u;
    asm("cvt.rna.tf32.f32 %0, %1;" : "=r"(u) : "f"(a));
    return u;
}
__device__ __forceinline__ void split_tf32(float a, uint32_t& h, uint32_t& l) {
    h = to_tf32(a);
    l = to_tf32(a - __uint_as_float(h));
}

#define MMA_TF32(d, a, b) \
    asm volatile("mma.sync.aligned.m16n8k8.row.col.f32.tf32.tf32.f32 " \
        "{%0,%1,%2,%3}, {%4,%5,%6,%7}, {%8,%9}, {%0,%1,%2,%3};" \
        : "+f"((d)[0]), "+f"((d)[1]), "+f"((d)[2]), "+f"((d)[3]) \
        : "r"((a)[0]), "r"((a)[1]), "r"((a)[2]), "r"((a)[3]), \
          "r"((b)[0]), "r"((b)[1]))

// ---------------- tensor GEMM via mma.sync (tf32 3-pass split) -------------
#define TGKC 16
#define SAS  20

__global__ __launch_bounds__(256, 1)
void tgemm(const float* __restrict__ A, const float* __restrict__ A2,
           const float* __restrict__ W, float* __restrict__ C,
           int N, int K, int accum)
{
    __shared__ float Ah[128*SAS];
    __shared__ float Al[128*SAS];
    __shared__ float Bh[128*SAS];
    __shared__ float Bl[128*SAS];

    const int tid = threadIdx.x;
    const int bm  = blockIdx.y * 128;
    const int bn  = blockIdx.x * 128;
    const int lr  = tid >> 1;
    const int lc  = (tid & 1) * 8;
    const int nck = (K + TGKC - 1) / TGKC;

    const int lane = tid & 31, wid = tid >> 5;
    const int g = lane >> 2, t = lane & 3;
    const int wm = (wid >> 1) * 32;
    const int wn = (wid & 1)  * 64;

    const float* arow  = A + (size_t)(bm + lr) * K;
    const float* a2row = A2 ? A2 + (size_t)(bm + lr) * K : (const float*)0;
    const bool   wv    = (bn + lr) < N;
    const float* wrow  = W + (size_t)(bn + lr) * K;

    float acc[2][8][4];
#pragma unroll
    for (int mt = 0; mt < 2; mt++)
#pragma unroll
        for (int nt = 0; nt < 8; nt++)
#pragma unroll
            for (int q = 0; q < 4; q++) acc[mt][nt][q] = 0.f;

    float4 va[2], vw[2];

    {
        int k0 = lc;
#pragma unroll
        for (int i = 0; i < 2; i++) {
            int gk = k0 + i*4;
            va[i] = ld4_guard(arow + gk, gk, K);
            if (a2row) {
                float4 v2 = ld4_guard(a2row + gk, gk, K);
                va[i].x += v2.x; va[i].y += v2.y; va[i].z += v2.z; va[i].w += v2.w;
            }
            vw[i] = wv ? ld4_guard(wrow + gk, gk, K) : make_float4(0.f,0.f,0.f,0.f);
        }
    }

    for (int ck = 0; ck < nck; ck++) {
#pragma unroll
        for (int i = 0; i < 2; i++) {
            int idx = lr*SAS + lc + i*4;
            uint32_t h0,l0,h1,l1,h2,l2,h3,l3;
            split_tf32(va[i].x, h0, l0); split_tf32(va[i].y, h1, l1);
            split_tf32(va[i].z, h2, l2); split_tf32(va[i].w, h3, l3);
            *(uint4*)&Ah[idx] = make_uint4(h0,h1,h2,h3);
            *(uint4*)&Al[idx] = make_uint4(l0,l1,l2,l3);
            split_tf32(vw[i].x, h0, l0); split_tf32(vw[i].y, h1, l1);
            split_tf32(vw[i].z, h2, l2); split_tf32(vw[i].w, h3, l3);
            *(uint4*)&Bh[idx] = make_uint4(h0,h1,h2,h3);
            *(uint4*)&Bl[idx] = make_uint4(l0,l1,l2,l3);
        }
        __syncthreads();

        if (ck + 1 < nck) {
            int k0 = (ck+1)*TGKC + lc;
#pragma unroll
            for (int i = 0; i < 2; i++) {
                int gk = k0 + i*4;
                va[i] = ld4_guard(arow + gk, gk, K);
                if (a2row) {
                    float4 v2 = ld4_guard(a2row + gk, gk, K);
                    va[i].x += v2.x; va[i].y += v2.y; va[i].z += v2.z; va[i].w += v2.w;
                }
                vw[i] = wv ? ld4_guard(wrow + gk, gk, K) : make_float4(0.f,0.f,0.f,0.f);
            }
        }

#pragma unroll
        for (int kk = 0; kk < TGKC; kk += 8) {
            uint32_t ah[2][4], al[2][4];
#pragma unroll
            for (int mt = 0; mt < 2; mt++) {
                int base = (wm + mt*16 + g)*SAS + kk + t;
                ah[mt][0] = __float_as_uint(Ah[base]);
                ah[mt][1] = __float_as_uint(Ah[base + 8*SAS]);
                ah[mt][2] = __float_as_uint(Ah[base + 4]);
                ah[mt][3] = __float_as_uint(Ah[base + 8*SAS + 4]);
                al[mt][0] = __float_as_uint(Al[base]);
                al[mt][1] = __float_as_uint(Al[base + 8*SAS]);
                al[mt][2] = __float_as_uint(Al[base + 4]);
                al[mt][3] = __float_as_uint(Al[base + 8*SAS + 4]);
            }
            uint32_t bh[8][2], bl[8][2];
#pragma unroll
            for (int nt = 0; nt < 8; nt++) {
                int nb = (wn + nt*8 + g)*SAS + kk + t;
                bh[nt][0] = __float_as_uint(Bh[nb]);
                bh[nt][1] = __float_as_uint(Bh[nb + 4]);
                bl[nt][0] = __float_as_uint(Bl[nb]);
                bl[nt][1] = __float_as_uint(Bl[nb + 4]);
            }
#pragma unroll
            for (int mt = 0; mt < 2; mt++)
#pragma unroll
                for (int nt = 0; nt < 8; nt++)
                    MMA_TF32(acc[mt][nt], ah[mt], bh[nt]);
#pragma unroll
            for (int mt = 0; mt < 2; mt++)
#pragma unroll
                for (int nt = 0; nt < 8; nt++)
                    MMA_TF32(acc[mt][nt], ah[mt], bl[nt]);
#pragma unroll
            for (int mt = 0; mt < 2; mt++)
#pragma unroll
                for (int nt = 0; nt < 8; nt++)
                    MMA_TF32(acc[mt][nt], al[mt], bh[nt]);
        }
        __syncthreads();
    }

#pragma unroll
    for (int mt = 0; mt < 2; mt++) {
        int row0 = bm + wm + mt*16 + g;
#pragma unroll
        for (int half = 0; half < 2; half++) {
            int rowg = row0 + half*8;
            float* crow = C + (size_t)rowg * N;
#pragma unroll
            for (int nt = 0; nt < 8; nt++) {
                int col = bn + wn + nt*8 + t*2;
                float v0 = acc[mt][nt][half*2 + 0];
                float v1 = acc[mt][nt][half*2 + 1];
                if (col + 1 < N) {
                    float2 v = make_float2(v0, v1);
                    if (accum) {
                        float2 o = *(const float2*)&crow[col];
                        v.x += o.x; v.y += o.y;
                    }
                    *(float2*)&crow[col] = v;
                } else if (col < N) {
                    float v = v0;
                    if (accum) v += crow[col];
                    crow[col] = v;
                }
            }
        }
    }
}

// ---------------- depthwise conv + SiLU;  also packs (D*xv, silu(z)) -------
__global__ void conv_silu_kernel(const float* __restrict__ cw,
                                 const float* __restrict__ cb,
                                 const float* __restrict__ Dp)
{
    int dir = blockIdx.y;
    int i = blockIdx.x*blockDim.x + threadIdx.x;
    if (i >= MROWS*ED) return;
    int m = i / ED, e = i - m*ED;
    int t = m & (LSEQ-1);
    float w0 = cw[e*4+0], w1 = cw[e*4+1], w2 = cw[e*4+2], w3 = cw[e*4+3];
    const float* xr = g_xz;
    float s = xr[(size_t)m*XZW + e] * w3;
    if (dir == 0) {
        if (t >= 1) s = fmaf(xr[(size_t)(m-1)*XZW + e], w2, s);
        if (t >= 2) s = fmaf(xr[(size_t)(m-2)*XZW + e], w1, s);
        if (t >= 3) s = fmaf(xr[(size_t)(m-3)*XZW + e], w0, s);
    } else {
        if (t+1 < LSEQ) s = fmaf(xr[(size_t)(m+1)*XZW + e], w2, s);
        if (t+2 < LSEQ) s = fmaf(xr[(size_t)(m+2)*XZW + e], w1, s);
        if (t+3 < LSEQ) s = fmaf(xr[(size_t)(m+3)*XZW + e], w0, s);
    }
    s += cb[e];
    float sv = s / (1.f + __expf(-s));
    g_xc[dir][i] = sv;
    // pack: z-gate + D*xv for the scan
    float zv = xr[(size_t)m*XZW + ED + e];
    float sz = zv / (1.f + __expf(-zv));
    *((float2*)&g_dx[dir][i] + 1) = make_float2(Dp[e]*sv, sz);
}

// ---------------- xproj: dbl[:, :30] + packed (B,C) ------------------------
__global__ __launch_bounds__(256)
void gemm_xproj(const float* __restrict__ W)
{
    const int dirq = blockIdx.y;
    const float* A   = &g_xc[dirq][0];
    float*       C   = &g_dbl[dirq][0];
    float2*      bc  = &g_bc[dirq][0];
    __shared__ float As[16][68];
    __shared__ float Ws[64][68];
    const int tid = threadIdx.x;
    const int bm  = blockIdx.x * 16;
    const int m   = tid & 15;
    const int nb  = tid >> 4;
    float acc[4] = {0.f, 0.f, 0.f, 0.f};

    for (int k0 = 0; k0 < ED; k0 += 64) {
        {
            int row = tid >> 4;
            int c   = (tid & 15) << 2;
            int k   = k0 + c;
            float4 v = ld4_guard(A + (size_t)(bm+row)*ED + k, k, ED);
            As[row][c+0] = v.x; As[row][c+1] = v.y; As[row][c+2] = v.z; As[row][c+3] = v.w;
        }
#pragma unroll
        for (int i = 0; i < 16; i++) {
            int lin = i*256 + tid;
            int n = lin >> 6, k = lin & 63;
            float v = 0.f;
            if (n < DBLW && (k0 + k) < ED) v = W[(size_t)n*ED + k0 + k];
            Ws[n][k] = v;
        }
        __syncthreads();
#pragma unroll
        for (int k = 0; k < 64; k++) {
            float a = As[m][k];
            acc[0] = fmaf(a, Ws[nb     ][k], acc[0]);
            acc[1] = fmaf(a, Ws[nb + 16][k], acc[1]);
            acc[2] = fmaf(a, Ws[nb + 32][k], acc[2]);
            acc[3] = fmaf(a, Ws[nb + 48][k], acc[3]);
        }
        __syncthreads();
    }
#pragma unroll
    for (int j = 0; j < 4; j++) {
        int n = nb + 16*j;
        size_t row = (size_t)(bm+m);
        if (n < RK) {
            C[row*DBLW + n] = acc[j];
        } else if (n < RK + NST) {
            bc[row*NST + (n - RK)].x = acc[j];
        } else if (n < DBLW) {
            bc[row*NST + (n - RK - NST)].y = acc[j];
        }
    }
}

// ---------------- dt: delta + packed (delta, delta*xv) ---------------------
__global__ __launch_bounds__(256)
void gemm_dt(const float* __restrict__ Wd, const float* __restrict__ dtb)
{
    const int dirq = blockIdx.z;
    const float* dbl = &g_dbl[dirq][0];
    const float* xcp = &g_xc[dirq][0];
    float4*      dx  = &g_dx[dirq][0];
    __shared__ float As[64][33];
    __shared__ float Ws[128][33];
    const int tid = threadIdx.x;
    const int bm  = blockIdx.y * 64;
    const int bn  = blockIdx.x * 128;
#pragma unroll
    for (int i = 0; i < 8; i++) {
        int lin = i*256 + tid;
        int r = lin >> 5, k = lin & 31;
        As[r][k] = (k < RK) ? dbl[(size_t)(bm+r)*DBLW + k] : 0.f;
    }
#pragma unroll
    for (int i = 0; i < 16; i++) {
        int lin = i*256 + tid;
        int n = lin >> 5, k = lin & 31;
        int gn = bn + n;
        float v = 0.f;
        if (k < RK && gn < ED) v = Wd[(size_t)gn*RK + k];
        Ws[n][k] = v;
    }
    __syncthreads();
    const int ty = tid >> 5;
    const int tx = tid & 31;
    float acc[8][4];
#pragma unroll
    for (int i = 0; i < 8; i++)
#pragma unroll
        for (int j = 0; j < 4; j++) acc[i][j] = 0.f;
#pragma unroll
    for (int k = 0; k < RK; k++) {
        float a[8], w[4];
#pragma unroll
        for (int i = 0; i < 8; i++) a[i] = As[ty*8+i][k];
#pragma unroll
        for (int j = 0; j < 4; j++) w[j] = Ws[tx*4+j][k];
#pragma unroll
        for (int i = 0; i < 8; i++)
#pragma unroll
            for (int j = 0; j < 4; j++) acc[i][j] = fmaf(a[i], w[j], acc[i][j]);
    }
#pragma unroll
    for (int i = 0; i < 8; i++) {
        size_t row = (size_t)(bm + ty*8 + i);
#pragma unroll
        for (int j = 0; j < 4; j++) {
            int n = bn + tx*4 + j;
            if (n < ED) {
                float v  = acc[i][j] + dtb[n];
                float sp = fmaxf(v, 0.f) + log1pf(__expf(-fabsf(v)));
                float xv = xcp[row*ED + n];
                *((float2*)&dx[row*ED + n]) = make_float2(sp, sp*xv);
            }
        }
    }
}

// ---------------- chunked parallel selective scan (packed operands) --------
__global__ __launch_bounds__(512)
void scan_kernel(const float* __restrict__ Alog)
{
    const int dir = blockIdx.y;
    const float4* dx = &g_dx[dir][0];
    const float2* bc = &g_bc[dir][0];
    float*        yout = &g_y[dir][0];

    __shared__ float sH[SCH][32];
    __shared__ float sP[SCH][32];

    const int wid  = threadIdx.x >> 5;
    const int lane = threadIdx.x & 31;
    const int half = lane >> 4;
    const int n    = lane & 15;
    const int c    = blockIdx.x * 2 + half;
    const int b    = c / ED;
    const int e    = c - b*ED;

    const float An2 = -__expf(Alog[e*NST + n]) * 1.4426950408889634f;
    const size_t mbase = (size_t)b * LSEQ;
    const int t0     = wid * SCL;
    const int tstart = dir ? (LSEQ-1 - t0) : t0;
    const ptrdiff_t sE = dir ? -(ptrdiff_t)ED  : (ptrdiff_t)ED;
    const ptrdiff_t sB = dir ? -(ptrdiff_t)NST : (ptrdiff_t)NST;
    const size_t mrow = mbase + tstart;

    // ---- pass A: local scan, track product of dA ----
    {
        const float2* pd = (const float2*)(dx + mrow*ED + e);   // reads (.x,.y)
        const float2* pb = bc + mrow*NST + n;
        const ptrdiff_t sE2 = sE * 2;
        float h = 0.f, P = 1.f;
#pragma unroll 4
        for (int i = 0; i < SCL; i++) {
            float2 d  = *pd;
            float  Bn = pb->x;
            float dA  = exp2f(d.x * An2);
            h = fmaf(dA, h, d.y * Bn);
            P *= dA;
            pd += sE2; pb += sB;
        }
        sH[wid][lane] = h;
        sP[wid][lane] = P;
    }
    __syncthreads();

    // ---- combine ----
    float hin = 0.f;
    for (int j = 0; j < wid; j++)
        hin = fmaf(sP[j][lane], hin, sH[j][lane]);

    // ---- pass B: replay chunk from hin, emit y ----
    {
        const float4* pd = dx + mrow*ED + e;
        const float2* pb = bc + mrow*NST + n;
        float*        py = yout + mrow*ED + e;
        float h = hin;
#pragma unroll 2
        for (int i = 0; i < SCL; i++) {
            float4 d  = *pd;
            float2 BC = *pb;
            float dA  = exp2f(d.x * An2);
            h = fmaf(dA, h, d.y * BC.x);
            float p = h * BC.y;
            p += __shfl_xor_sync(0xffffffffu, p, 8, 16);
            p += __shfl_xor_sync(0xffffffffu, p, 4, 16);
            p += __shfl_xor_sync(0xffffffffu, p, 2, 16);
            p += __shfl_xor_sync(0xffffffffu, p, 1, 16);
            if (n == 0) *py = (p + d.z) * d.w;
            pd += sE; pb += sB; py += sE;
        }
    }
}

// ---------------- host orchestration ----------------
struct BlkP { const float *ip, *cw, *cb, *xp, *dw, *db, *al, *dd, *op; };

static void run_block_host(const BlkP& p, bool bidir,
                           float* hbuf, float* xzbuf, float* y0, float* y1)
{
    int ndir = bidir ? 2 : 1;
    tgemm<<<dim3(15, 32), 256>>>(hbuf, nullptr, p.ip, xzbuf, XZW, DIMV, 0);
    conv_silu_kernel<<<dim3((MROWS*ED + 255)/256, ndir), 256>>>(p.cw, p.cb, p.dd);
    gemm_xproj<<<dim3(MROWS/16, ndir), 256>>>(p.xp);
    gemm_dt<<<dim3(8, MROWS/64, ndir), 256>>>(p.dw, p.db);
    scan_kernel<<<dim3(944, ndir), 512>>>(p.al);
    tgemm<<<dim3(4, 32), 256>>>(y0, bidir ? y1 : nullptr, p.op, hbuf, DIMV, ED, 1);
}

extern "C" void kernel_launch(void* const* d_in, const int* in_sizes, int n_in,
                              void* d_out, int out_size)
{
    const float* x   = (const float*)d_in[0];
    const float* pw  = (const float*)d_in[1];
    const float* pb  = (const float*)d_in[2];
    const float* lmw = (const float*)d_in[3];
    const float* P[3][9];
    for (int g = 0; g < 3; g++)
        for (int i = 0; i < 9; i++)
            P[g][i] = (const float*)d_in[4 + g*9 + i];

    float *hbuf, *xzbuf, *ybuf;
    cudaGetSymbolAddress((void**)&hbuf,  g_h);
    cudaGetSymbolAddress((void**)&xzbuf, g_xz);
    cudaGetSymbolAddress((void**)&ybuf,  g_y);
    float* y0 = ybuf;
    float* y1 = ybuf + (size_t)MROWS*ED;

    patch_kernel<<<(MROWS*DIMV + 255)/256, 256>>>(x, pw, pb);

    {
        BlkP p = { P[0][0], P[0][1], P[0][2], P[0][3], P[0][4], P[0][5], P[0][6], P[0][7], P[0][8] };
        run_block_host(p, true, hbuf, xzbuf, y0, y1);
    }
    for (int l = 0; l < NDEPTH; l++) {
        BlkP p = {
            P[1][0] + (size_t)l*XZW*DIMV,
            P[1][1] + (size_t)l*ED*4,
            P[1][2] + (size_t)l*ED,
            P[1][3] + (size_t)l*DBLW*ED,
            P[1][4] + (size_t)l*ED*RK,
            P[1][5] + (size_t)l*ED,
            P[1][6] + (size_t)l*ED*NST,
            P[1][7] + (size_t)l*ED,
            P[1][8] + (size_t)l*DIMV*ED
        };
        run_block_host(p, false, hbuf, xzbuf, y0, y1);
    }
    {
        BlkP p = { P[2][0], P[2][1], P[2][2], P[2][3], P[2][4], P[2][5], P[2][6], P[2][7], P[2][8] };
        run_block_host(p, true, hbuf, xzbuf, y0, y1);
    }

    tgemm<<<dim3(4, 32), 256>>>(hbuf, nullptr, lmw, (float*)d_out, DIMV, DIMV, 0);
}

// round 13
// speedup vs baseline: 1.2654x; 1.0428x over previous
#include <cuda_runtime.h>
#include <cstdint>
#include <cstddef>

// ---------------- problem constants ----------------
#define BSZ   2
#define LSEQ  2048
#define DIMV  472          // DIM == V
#define ED    944
#define NST   16
#define RK    30
#define NDEPTH 8
#define MROWS (BSZ*LSEQ)   // 4096
#define XZW   (2*ED)       // 1888
#define DBLW  (RK + 2*NST) // 62

// scan chunking: 16 chunks of 128 steps, one warp per chunk
#define SCH   16
#define SCL   (LSEQ/SCH)   // 128

// ---------------- scratch (device globals: allocation-free) ----------------
__device__ float  g_h[(size_t)MROWS*DIMV];
__device__ float  g_xz[(size_t)MROWS*XZW];
__device__ float  g_xc[2][(size_t)MROWS*ED];
__device__ float4 g_dx[2][(size_t)MROWS*ED];     // (delta, delta*xv, D*xv, silu(z))
__device__ float2 g_bc[2][(size_t)MROWS*NST];    // (B_n, C_n)
__device__ float  g_y[2][(size_t)MROWS*ED];

// ---------------- patch embed ----------------
__global__ void patch_kernel(const float* __restrict__ x,
                             const float* __restrict__ pw,
                             const float* __restrict__ pb)
{
    int i = blockIdx.x*blockDim.x + threadIdx.x;
    if (i >= MROWS*DIMV) return;
    int m = i / DIMV, v = i - m*DIMV;
    const float* xr = x + (size_t)m*9;
    const float* wr = pw + (size_t)v*9;
    float s = pb[v];
#pragma unroll
    for (int k = 0; k < 9; k++) s = fmaf(xr[k], wr[k], s);
    g_h[i] = s;
}

__device__ __forceinline__ float4 ld4_guard(const float* p, int k0, int K)
{
    float4 v = make_float4(0.f, 0.f, 0.f, 0.f);
    if (k0 + 3 < K) v = *(const float4*)p;
    else if (k0 < K) {
        v.x = p[0];
        if (k0 + 1 < K) v.y = p[1];
        if (k0 + 2 < K) v.z = p[2];
    }
    return v;
}

// ---------------- tf32-split helpers ----------------
__device__ __forceinline__ uint32_t to_tf32(float a) {
    uint32_t u;
    asm("cvt.rna.tf32.f32 %0, %1;" : "=r"(u) : "f"(a));
    return u;
}
__device__ __forceinline__ void split_tf32(float a, uint32_t& h, uint32_t& l) {
    h = to_tf32(a);
    l = to_tf32(a - __uint_as_float(h));
}

#define MMA_TF32(d, a, b) \
    asm volatile("mma.sync.aligned.m16n8k8.row.col.f32.tf32.tf32.f32 " \
        "{%0,%1,%2,%3}, {%4,%5,%6,%7}, {%8,%9}, {%0,%1,%2,%3};" \
        : "+f"((d)[0]), "+f"((d)[1]), "+f"((d)[2]), "+f"((d)[3]) \
        : "r"((a)[0]), "r"((a)[1]), "r"((a)[2]), "r"((a)[3]), \
          "r"((b)[0]), "r"((b)[1]))

// ---------------- tensor GEMM via mma.sync (tf32 3-pass split) -------------
#define TGKC 16
#define SAS  20

__global__ __launch_bounds__(256, 1)
void tgemm(const float* __restrict__ A, const float* __restrict__ A2,
           const float* __restrict__ W, float* __restrict__ C,
           int N, int K, int accum)
{
    __shared__ float Ah[128*SAS];
    __shared__ float Al[128*SAS];
    __shared__ float Bh[128*SAS];
    __shared__ float Bl[128*SAS];

    const int tid = threadIdx.x;
    const int bm  = blockIdx.y * 128;
    const int bn  = blockIdx.x * 128;
    const int lr  = tid >> 1;
    const int lc  = (tid & 1) * 8;
    const int nck = (K + TGKC - 1) / TGKC;

    const int lane = tid & 31, wid = tid >> 5;
    const int g = lane >> 2, t = lane & 3;
    const int wm = (wid >> 1) * 32;
    const int wn = (wid & 1)  * 64;

    const float* arow  = A + (size_t)(bm + lr) * K;
    const float* a2row = A2 ? A2 + (size_t)(bm + lr) * K : (const float*)0;
    const bool   wv    = (bn + lr) < N;
    const float* wrow  = W + (size_t)(bn + lr) * K;

    float acc[2][8][4];
#pragma unroll
    for (int mt = 0; mt < 2; mt++)
#pragma unroll
        for (int nt = 0; nt < 8; nt++)
#pragma unroll
            for (int q = 0; q < 4; q++) acc[mt][nt][q] = 0.f;

    float4 va[2], vw[2];

    {
        int k0 = lc;
#pragma unroll
        for (int i = 0; i < 2; i++) {
            int gk = k0 + i*4;
            va[i] = ld4_guard(arow + gk, gk, K);
            if (a2row) {
                float4 v2 = ld4_guard(a2row + gk, gk, K);
                va[i].x += v2.x; va[i].y += v2.y; va[i].z += v2.z; va[i].w += v2.w;
            }
            vw[i] = wv ? ld4_guard(wrow + gk, gk, K) : make_float4(0.f,0.f,0.f,0.f);
        }
    }

    for (int ck = 0; ck < nck; ck++) {
#pragma unroll
        for (int i = 0; i < 2; i++) {
            int idx = lr*SAS + lc + i*4;
            uint32_t h0,l0,h1,l1,h2,l2,h3,l3;
            split_tf32(va[i].x, h0, l0); split_tf32(va[i].y, h1, l1);
            split_tf32(va[i].z, h2, l2); split_tf32(va[i].w, h3, l3);
            *(uint4*)&Ah[idx] = make_uint4(h0,h1,h2,h3);
            *(uint4*)&Al[idx] = make_uint4(l0,l1,l2,l3);
            split_tf32(vw[i].x, h0, l0); split_tf32(vw[i].y, h1, l1);
            split_tf32(vw[i].z, h2, l2); split_tf32(vw[i].w, h3, l3);
            *(uint4*)&Bh[idx] = make_uint4(h0,h1,h2,h3);
            *(uint4*)&Bl[idx] = make_uint4(l0,l1,l2,l3);
        }
        __syncthreads();

        if (ck + 1 < nck) {
            int k0 = (ck+1)*TGKC + lc;
#pragma unroll
            for (int i = 0; i < 2; i++) {
                int gk = k0 + i*4;
                va[i] = ld4_guard(arow + gk, gk, K);
                if (a2row) {
                    float4 v2 = ld4_guard(a2row + gk, gk, K);
                    va[i].x += v2.x; va[i].y += v2.y; va[i].z += v2.z; va[i].w += v2.w;
                }
                vw[i] = wv ? ld4_guard(wrow + gk, gk, K) : make_float4(0.f,0.f,0.f,0.f);
            }
        }

#pragma unroll
        for (int kk = 0; kk < TGKC; kk += 8) {
            uint32_t ah[2][4], al[2][4];
#pragma unroll
            for (int mt = 0; mt < 2; mt++) {
                int base = (wm + mt*16 + g)*SAS + kk + t;
                ah[mt][0] = __float_as_uint(Ah[base]);
                ah[mt][1] = __float_as_uint(Ah[base + 8*SAS]);
                ah[mt][2] = __float_as_uint(Ah[base + 4]);
                ah[mt][3] = __float_as_uint(Ah[base + 8*SAS + 4]);
                al[mt][0] = __float_as_uint(Al[base]);
                al[mt][1] = __float_as_uint(Al[base + 8*SAS]);
                al[mt][2] = __float_as_uint(Al[base + 4]);
                al[mt][3] = __float_as_uint(Al[base + 8*SAS + 4]);
            }
            uint32_t bh[8][2], bl[8][2];
#pragma unroll
            for (int nt = 0; nt < 8; nt++) {
                int nb = (wn + nt*8 + g)*SAS + kk + t;
                bh[nt][0] = __float_as_uint(Bh[nb]);
                bh[nt][1] = __float_as_uint(Bh[nb + 4]);
                bl[nt][0] = __float_as_uint(Bl[nb]);
                bl[nt][1] = __float_as_uint(Bl[nb + 4]);
            }
#pragma unroll
            for (int mt = 0; mt < 2; mt++)
#pragma unroll
                for (int nt = 0; nt < 8; nt++)
                    MMA_TF32(acc[mt][nt], ah[mt], bh[nt]);
#pragma unroll
            for (int mt = 0; mt < 2; mt++)
#pragma unroll
                for (int nt = 0; nt < 8; nt++)
                    MMA_TF32(acc[mt][nt], ah[mt], bl[nt]);
#pragma unroll
            for (int mt = 0; mt < 2; mt++)
#pragma unroll
                for (int nt = 0; nt < 8; nt++)
                    MMA_TF32(acc[mt][nt], al[mt], bh[nt]);
        }
        __syncthreads();
    }

#pragma unroll
    for (int mt = 0; mt < 2; mt++) {
        int row0 = bm + wm + mt*16 + g;
#pragma unroll
        for (int half = 0; half < 2; half++) {
            int rowg = row0 + half*8;
            float* crow = C + (size_t)rowg * N;
#pragma unroll
            for (int nt = 0; nt < 8; nt++) {
                int col = bn + wn + nt*8 + t*2;
                float v0 = acc[mt][nt][half*2 + 0];
                float v1 = acc[mt][nt][half*2 + 1];
                if (col + 1 < N) {
                    float2 v = make_float2(v0, v1);
                    if (accum) {
                        float2 o = *(const float2*)&crow[col];
                        v.x += o.x; v.y += o.y;
                    }
                    *(float2*)&crow[col] = v;
                } else if (col < N) {
                    float v = v0;
                    if (accum) v += crow[col];
                    crow[col] = v;
                }
            }
        }
    }
}

// ---------------- depthwise conv + SiLU (float2) + packs (D*xv, silu(z)) ---
__global__ void conv_silu_kernel(const float* __restrict__ cw,
                                 const float* __restrict__ cb,
                                 const float* __restrict__ Dp)
{
    int dir = blockIdx.y;
    int i = blockIdx.x*blockDim.x + threadIdx.x;    // channel-pair index
    if (i >= MROWS*(ED/2)) return;
    int m = i / (ED/2), ep = i - m*(ED/2);
    int e = ep * 2;
    int t = m & (LSEQ-1);

    float4 cwa = *(const float4*)(cw + e*4);
    float4 cwb = *(const float4*)(cw + e*4 + 4);
    const float* xr = g_xz + (size_t)m*XZW + e;

    float2 x0 = *(const float2*)xr;
    float sx = x0.x * cwa.w, sy = x0.y * cwb.w;
    if (dir == 0) {
        if (t >= 1) { float2 v = *(const float2*)(xr - XZW);   sx = fmaf(v.x, cwa.z, sx); sy = fmaf(v.y, cwb.z, sy); }
        if (t >= 2) { float2 v = *(const float2*)(xr - 2*XZW); sx = fmaf(v.x, cwa.y, sx); sy = fmaf(v.y, cwb.y, sy); }
        if (t >= 3) { float2 v = *(const float2*)(xr - 3*XZW); sx = fmaf(v.x, cwa.x, sx); sy = fmaf(v.y, cwb.x, sy); }
    } else {
        if (t+1 < LSEQ) { float2 v = *(const float2*)(xr + XZW);   sx = fmaf(v.x, cwa.z, sx); sy = fmaf(v.y, cwb.z, sy); }
        if (t+2 < LSEQ) { float2 v = *(const float2*)(xr + 2*XZW); sx = fmaf(v.x, cwa.y, sx); sy = fmaf(v.y, cwb.y, sy); }
        if (t+3 < LSEQ) { float2 v = *(const float2*)(xr + 3*XZW); sx = fmaf(v.x, cwa.x, sx); sy = fmaf(v.y, cwb.x, sy); }
    }
    float2 cbv = *(const float2*)(cb + e);
    sx += cbv.x; sy += cbv.y;
    float svx = sx / (1.f + __expf(-sx));
    float svy = sy / (1.f + __expf(-sy));
    size_t o = (size_t)m*ED + e;
    *(float2*)&g_xc[dir][o] = make_float2(svx, svy);

    float2 zv = *(const float2*)(g_xz + (size_t)m*XZW + ED + e);
    float szx = zv.x / (1.f + __expf(-zv.x));
    float szy = zv.y / (1.f + __expf(-zv.y));
    float2 Dv = *(const float2*)(Dp + e);
    *((float2*)&g_dx[dir][o]     + 1) = make_float2(Dv.x*svx, szx);
    *((float2*)&g_dx[dir][o + 1] + 1) = make_float2(Dv.y*svy, szy);
}

// ---------------- fused xproj + dt:  dbl -> smem, (B,C) -> g_bc, -----------
// delta -> g_dx.xy.  Same grid/occupancy as the old xproj kernel.
__global__ __launch_bounds__(256)
void gemm_xproj_dt(const float* __restrict__ W,
                   const float* __restrict__ Wd, const float* __restrict__ dtb)
{
    const int dirq = blockIdx.y;
    const float* A   = &g_xc[dirq][0];
    float2*      bc  = &g_bc[dirq][0];
    float4*      dx  = &g_dx[dirq][0];
    __shared__ float As[16][68];
    __shared__ float Ws[64][68];
    __shared__ float dbls[16][32];
    const int tid = threadIdx.x;
    const int bm  = blockIdx.x * 16;
    const int m   = tid & 15;
    const int nb  = tid >> 4;
    float acc[4] = {0.f, 0.f, 0.f, 0.f};

    // ---- phase 1: xproj (identical math to the old kernel) ----
    for (int k0 = 0; k0 < ED; k0 += 64) {
        {
            int row = tid >> 4;
            int c   = (tid & 15) << 2;
            int k   = k0 + c;
            float4 v = ld4_guard(A + (size_t)(bm+row)*ED + k, k, ED);
            As[row][c+0] = v.x; As[row][c+1] = v.y; As[row][c+2] = v.z; As[row][c+3] = v.w;
        }
#pragma unroll
        for (int i = 0; i < 16; i++) {
            int lin = i*256 + tid;
            int n = lin >> 6, k = lin & 63;
            float v = 0.f;
            if (n < DBLW && (k0 + k) < ED) v = W[(size_t)n*ED + k0 + k];
            Ws[n][k] = v;
        }
        __syncthreads();
#pragma unroll
        for (int k = 0; k < 64; k++) {
            float a = As[m][k];
            acc[0] = fmaf(a, Ws[nb     ][k], acc[0]);
            acc[1] = fmaf(a, Ws[nb + 16][k], acc[1]);
            acc[2] = fmaf(a, Ws[nb + 32][k], acc[2]);
            acc[3] = fmaf(a, Ws[nb + 48][k], acc[3]);
        }
        __syncthreads();
    }
#pragma unroll
    for (int j = 0; j < 4; j++) {
        int n = nb + 16*j;
        size_t row = (size_t)(bm+m);
        if (n < RK) {
            dbls[m][n] = acc[j];
        } else if (n < RK + NST) {
            bc[row*NST + (n - RK)].x = acc[j];
        } else if (n < DBLW) {
            bc[row*NST + (n - RK - NST)].y = acc[j];
        }
    }
    __syncthreads();

    // ---- phase 2: dt (softplus(dbl[:, :30] @ Wd^T + b)) + delta packing ----
    for (int j = tid; j < ED; j += 256) {
        const float* wr = Wd + (size_t)j*RK;
        float wj[RK];
#pragma unroll
        for (int k = 0; k < RK; k += 2) {
            float2 v = *(const float2*)&wr[k];
            wj[k] = v.x; wj[k+1] = v.y;
        }
        float bj = dtb[j];
#pragma unroll 4
        for (int r = 0; r < 16; r++) {
            float a = bj;
#pragma unroll
            for (int k = 0; k < RK; k++) a = fmaf(dbls[r][k], wj[k], a);
            float sp = fmaxf(a, 0.f) + log1pf(__expf(-fabsf(a)));
            size_t row = (size_t)(bm + r);
            float xv = A[row*ED + j];
            *((float2*)&dx[row*ED + j]) = make_float2(sp, sp*xv);
        }
    }
}

// ---------------- chunked parallel selective scan (packed operands) --------
__global__ __launch_bounds__(512)
void scan_kernel(const float* __restrict__ Alog)
{
    const int dir = blockIdx.y;
    const float4* dx = &g_dx[dir][0];
    const float2* bc = &g_bc[dir][0];
    float*        yout = &g_y[dir][0];

    __shared__ float sH[SCH][32];
    __shared__ float sP[SCH][32];

    const int wid  = threadIdx.x >> 5;
    const int lane = threadIdx.x & 31;
    const int half = lane >> 4;
    const int n    = lane & 15;
    const int c    = blockIdx.x * 2 + half;
    const int b    = c / ED;
    const int e    = c - b*ED;

    const float An2 = -__expf(Alog[e*NST + n]) * 1.4426950408889634f;
    const size_t mbase = (size_t)b * LSEQ;
    const int t0     = wid * SCL;
    const int tstart = dir ? (LSEQ-1 - t0) : t0;
    const ptrdiff_t sE = dir ? -(ptrdiff_t)ED  : (ptrdiff_t)ED;
    const ptrdiff_t sB = dir ? -(ptrdiff_t)NST : (ptrdiff_t)NST;
    const size_t mrow = mbase + tstart;

    // ---- pass A: local scan, track product of dA ----
    {
        const float2* pd = (const float2*)(dx + mrow*ED + e);   // reads (.x,.y)
        const float2* pb = bc + mrow*NST + n;
        const ptrdiff_t sE2 = sE * 2;
        float h = 0.f, P = 1.f;
#pragma unroll 4
        for (int i = 0; i < SCL; i++) {
            float2 d  = *pd;
            float  Bn = pb->x;
            float dA  = exp2f(d.x * An2);
            h = fmaf(dA, h, d.y * Bn);
            P *= dA;
            pd += sE2; pb += sB;
        }
        sH[wid][lane] = h;
        sP[wid][lane] = P;
    }
    __syncthreads();

    // ---- combine ----
    float hin = 0.f;
    for (int j = 0; j < wid; j++)
        hin = fmaf(sP[j][lane], hin, sH[j][lane]);

    // ---- pass B: replay chunk from hin, emit y ----
    {
        const float4* pd = dx + mrow*ED + e;
        const float2* pb = bc + mrow*NST + n;
        float*        py = yout + mrow*ED + e;
        float h = hin;
#pragma unroll 2
        for (int i = 0; i < SCL; i++) {
            float4 d  = *pd;
            float2 BC = *pb;
            float dA  = exp2f(d.x * An2);
            h = fmaf(dA, h, d.y * BC.x);
            float p = h * BC.y;
            p += __shfl_xor_sync(0xffffffffu, p, 8, 16);
            p += __shfl_xor_sync(0xffffffffu, p, 4, 16);
            p += __shfl_xor_sync(0xffffffffu, p, 2, 16);
            p += __shfl_xor_sync(0xffffffffu, p, 1, 16);
            if (n == 0) *py = (p + d.z) * d.w;
            pd += sE; pb += sB; py += sE;
        }
    }
}

// ---------------- host orchestration ----------------
struct BlkP { const float *ip, *cw, *cb, *xp, *dw, *db, *al, *dd, *op; };

static void run_block_host(const BlkP& p, bool bidir,
                           float* hbuf, float* xzbuf, float* y0, float* y1)
{
    int ndir = bidir ? 2 : 1;
    tgemm<<<dim3(15, 32), 256>>>(hbuf, nullptr, p.ip, xzbuf, XZW, DIMV, 0);
    conv_silu_kernel<<<dim3((MROWS*(ED/2) + 255)/256, ndir), 256>>>(p.cw, p.cb, p.dd);
    gemm_xproj_dt<<<dim3(MROWS/16, ndir), 256>>>(p.xp, p.dw, p.db);
    scan_kernel<<<dim3(944, ndir), 512>>>(p.al);
    tgemm<<<dim3(4, 32), 256>>>(y0, bidir ? y1 : nullptr, p.op, hbuf, DIMV, ED, 1);
}

extern "C" void kernel_launch(void* const* d_in, const int* in_sizes, int n_in,
                              void* d_out, int out_size)
{
    const float* x   = (const float*)d_in[0];
    const float* pw  = (const float*)d_in[1];
    const float* pb  = (const float*)d_in[2];
    const float* lmw = (const float*)d_in[3];
    const float* P[3][9];
    for (int g = 0; g < 3; g++)
        for (int i = 0; i < 9; i++)
            P[g][i] = (const float*)d_in[4 + g*9 + i];

    float *hbuf, *xzbuf, *ybuf;
    cudaGetSymbolAddress((void**)&hbuf,  g_h);
    cudaGetSymbolAddress((void**)&xzbuf, g_xz);
    cudaGetSymbolAddress((void**)&ybuf,  g_y);
    float* y0 = ybuf;
    float* y1 = ybuf + (size_t)MROWS*ED;

    patch_kernel<<<(MROWS*DIMV + 255)/256, 256>>>(x, pw, pb);

    {
        BlkP p = { P[0][0], P[0][1], P[0][2], P[0][3], P[0][4], P[0][5], P[0][6], P[0][7], P[0][8] };
        run_block_host(p, true, hbuf, xzbuf, y0, y1);
    }
    for (int l = 0; l < NDEPTH; l++) {
        BlkP p = {
            P[1][0] + (size_t)l*XZW*DIMV,
            P[1][1] + (size_t)l*ED*4,
            P[1][2] + (size_t)l*ED,
            P[1][3] + (size_t)l*DBLW*ED,
            P[1][4] + (size_t)l*ED*RK,
            P[1][5] + (size_t)l*ED,
            P[1][6] + (size_t)l*ED*NST,
            P[1][7] + (size_t)l*ED,
            P[1][8] + (size_t)l*DIMV*ED
        };
        run_block_host(p, false, hbuf, xzbuf, y0, y1);
    }
    {
        BlkP p = { P[2][0], P[2][1], P[2][2], P[2][3], P[2][4], P[2][5], P[2][6], P[2][7], P[2][8] };
        run_block_host(p, true, hbuf, xzbuf, y0, y1);
    }

    tgemm<<<dim3(4, 32), 256>>>(hbuf, nullptr, lmw, (float*)d_out, DIMV, DIMV, 0);
}